// round 2
// baseline (speedup 1.0000x reference)
#include <cuda_runtime.h>
#include <math.h>

namespace {
constexpr int Bsz  = 8;
constexpr int Lsz  = 1024;
constexpr int Hsz  = 8;
constexpr int Esz  = 64;
constexpr int HIST = 512;
constexpr float SCALE = 0.125f;   // 1/sqrt(64)
constexpr int TILE = 64;
constexpr int STR  = 65;          // smem row stride (floats) — breaks bank conflicts
constexpr int SMEM_BYTES = 4 * TILE * STR * 4;  // Qs,Ks,Vs,Ps
}

__global__ __launch_bounds__(256, 3)
void fftcc_attn_kernel(const float* __restrict__ Q,  const float* __restrict__ K,
                       const float* __restrict__ V,  const float* __restrict__ QD,
                       const float* __restrict__ KD, const float* __restrict__ VD,
                       float* __restrict__ Out)
{
    extern __shared__ float sm[];
    float* Qs = sm;
    float* Ks = Qs + TILE * STR;
    float* Vs = Ks + TILE * STR;
    float* Ps = Vs + TILE * STR;

    const int bh = blockIdx.y;          // b*H + h
    const int b  = bh >> 3;
    const int h  = bh & 7;
    // heaviest q-tiles first for wave balance
    const int m0  = (int)(gridDim.x - 1 - blockIdx.x) * TILE;
    const int tid = threadIdx.x;
    const int ty  = tid >> 4;           // 0..15 -> q-row group
    const int tx  = tid & 15;           // 0..15 -> col group
    const int rs  = Hsz * Esz;          // 512: stride between sequence positions
    const int base = (b * Lsz * Hsz + h) * Esz;

    // ---- Load Q tile (q_eff: queries below HIST, queries_drawn above) ----
    {
        const int r0 = tid >> 4;
        const int c4 = (tid & 15) << 2;
        #pragma unroll
        for (int it = 0; it < 4; ++it) {
            const int r = r0 + it * 16;
            const int l = m0 + r;
            const float* src = (l < HIST) ? Q : QD;
            const float4 val = *reinterpret_cast<const float4*>(src + base + l * rs + c4);
            float* d = Qs + r * STR + c4;
            d[0] = val.x; d[1] = val.y; d[2] = val.z; d[3] = val.w;
        }
    }
    __syncthreads();

    // ---- Precompute diagonal replacement scores: dot(q_eff[l], keys_drawn[l]) ----
    // Only meaningful on threads with tx==ty (they own the (i==j) diag sub-elements).
    const bool has_diag_repl = (m0 >= HIST);
    float dS[4] = {0.f, 0.f, 0.f, 0.f};
    if (has_diag_repl && tx == ty) {
        #pragma unroll
        for (int i = 0; i < 4; ++i) {
            const int r = (ty << 2) + i;
            const int l = m0 + r;
            const float* kr = KD + base + l * rs;
            const float* qr = Qs + r * STR;
            float acc = 0.f;
            #pragma unroll
            for (int e4 = 0; e4 < 16; ++e4) {
                const float4 kv = *reinterpret_cast<const float4*>(kr + (e4 << 2));
                acc += qr[(e4 << 2) + 0] * kv.x + qr[(e4 << 2) + 1] * kv.y
                     + qr[(e4 << 2) + 2] * kv.z + qr[(e4 << 2) + 3] * kv.w;
            }
            dS[i] = acc;
        }
    }

    float O[4][4];
    float mrow[4], lsum[4];
    #pragma unroll
    for (int i = 0; i < 4; ++i) {
        mrow[i] = -INFINITY;
        lsum[i] = 0.f;
        #pragma unroll
        for (int j = 0; j < 4; ++j) O[i][j] = 0.f;
    }

    const int ntiles = (m0 >> 6) + 1;
    for (int t = 0; t < ntiles; ++t) {
        const int n0 = t << 6;
        const bool diag = (n0 == m0);

        __syncthreads();   // protect Ks/Vs/Ps from previous iteration's readers
        // ---- Load K,V tiles ----
        {
            const int r0 = tid >> 4;
            const int c4 = (tid & 15) << 2;
            #pragma unroll
            for (int it = 0; it < 4; ++it) {
                const int r = r0 + it * 16;
                const int g = base + (n0 + r) * rs + c4;
                const float4 kv = *reinterpret_cast<const float4*>(K + g);
                const float4 vv = *reinterpret_cast<const float4*>(V + g);
                float* dk = Ks + r * STR + c4;
                float* dv = Vs + r * STR + c4;
                dk[0] = kv.x; dk[1] = kv.y; dk[2] = kv.z; dk[3] = kv.w;
                dv[0] = vv.x; dv[1] = vv.y; dv[2] = vv.z; dv[3] = vv.w;
            }
        }
        __syncthreads();

        // ---- S = Q @ K^T (4x4 per thread) ----
        float S[4][4];
        #pragma unroll
        for (int i = 0; i < 4; ++i)
            #pragma unroll
            for (int j = 0; j < 4; ++j) S[i][j] = 0.f;

        #pragma unroll 8
        for (int e = 0; e < TILE; ++e) {
            float qv[4], kv[4];
            #pragma unroll
            for (int i = 0; i < 4; ++i) qv[i] = Qs[((ty << 2) + i) * STR + e];
            #pragma unroll
            for (int j = 0; j < 4; ++j) kv[j] = Ks[((tx << 2) + j) * STR + e];
            #pragma unroll
            for (int i = 0; i < 4; ++i)
                #pragma unroll
                for (int j = 0; j < 4; ++j) S[i][j] += qv[i] * kv[j];
        }

        // ---- diagonal substitution (pre-scale), scale, causal mask ----
        if (diag && has_diag_repl && tx == ty) {
            #pragma unroll
            for (int i = 0; i < 4; ++i) S[i][i] = dS[i];
        }
        #pragma unroll
        for (int i = 0; i < 4; ++i)
            #pragma unroll
            for (int j = 0; j < 4; ++j) S[i][j] *= SCALE;
        if (diag) {
            #pragma unroll
            for (int i = 0; i < 4; ++i)
                #pragma unroll
                for (int j = 0; j < 4; ++j)
                    if (((tx << 2) + j) > ((ty << 2) + i)) S[i][j] = -INFINITY;
        }

        // ---- online softmax (row reductions across tx via 16-lane xor shuffles) ----
        #pragma unroll
        for (int i = 0; i < 4; ++i) {
            float mx = fmaxf(fmaxf(S[i][0], S[i][1]), fmaxf(S[i][2], S[i][3]));
            #pragma unroll
            for (int o = 8; o > 0; o >>= 1)
                mx = fmaxf(mx, __shfl_xor_sync(0xffffffffu, mx, o));
            const float nm   = fmaxf(mrow[i], mx);
            const float corr = __expf(mrow[i] - nm);   // exp(-inf)=0 on first tile
            mrow[i] = nm;
            float rsum = 0.f;
            #pragma unroll
            for (int j = 0; j < 4; ++j) {
                const float p = __expf(S[i][j] - nm);  // masked -inf -> 0
                S[i][j] = p;
                rsum += p;
            }
            #pragma unroll
            for (int o = 8; o > 0; o >>= 1)
                rsum += __shfl_xor_sync(0xffffffffu, rsum, o);
            lsum[i] = lsum[i] * corr + rsum;
            #pragma unroll
            for (int j = 0; j < 4; ++j) O[i][j] *= corr;
            float* pr = Ps + ((ty << 2) + i) * STR + (tx << 2);
            pr[0] = S[i][0]; pr[1] = S[i][1]; pr[2] = S[i][2]; pr[3] = S[i][3];
        }
        __syncthreads();

        // ---- O += P @ V ----
        #pragma unroll 8
        for (int s = 0; s < TILE; ++s) {
            float pv[4], vv[4];
            #pragma unroll
            for (int i = 0; i < 4; ++i) pv[i] = Ps[((ty << 2) + i) * STR + s];
            #pragma unroll
            for (int j = 0; j < 4; ++j) vv[j] = Vs[s * STR + (tx << 2) + j];
            #pragma unroll
            for (int i = 0; i < 4; ++i)
                #pragma unroll
                for (int j = 0; j < 4; ++j) O[i][j] += pv[i] * vv[j];
        }

        // ---- diagonal value substitution: O += P[l][l] * (values_drawn[l] - values[l]) ----
        // Diag tile is the LAST tile, so this term needs no further max-rescale.
        if (diag && has_diag_repl) {
            #pragma unroll
            for (int i = 0; i < 4; ++i) {
                const int r = (ty << 2) + i;
                const int l = m0 + r;
                const float pd = Ps[r * STR + r];
                const float4 vdr = *reinterpret_cast<const float4*>(VD + base + l * rs + (tx << 2));
                O[i][0] += pd * (vdr.x - Vs[r * STR + (tx << 2) + 0]);
                O[i][1] += pd * (vdr.y - Vs[r * STR + (tx << 2) + 1]);
                O[i][2] += pd * (vdr.z - Vs[r * STR + (tx << 2) + 2]);
                O[i][3] += pd * (vdr.w - Vs[r * STR + (tx << 2) + 3]);
            }
        }
    }

    // ---- epilogue: normalize and store ----
    #pragma unroll
    for (int i = 0; i < 4; ++i) {
        const int r = (ty << 2) + i;
        const int l = m0 + r;
        const float inv = 1.0f / lsum[i];
        const float4 o4 = make_float4(O[i][0] * inv, O[i][1] * inv,
                                      O[i][2] * inv, O[i][3] * inv);
        *reinterpret_cast<float4*>(Out + base + l * rs + (tx << 2)) = o4;
    }
}

extern "C" void kernel_launch(void* const* d_in, const int* in_sizes, int n_in,
                              void* d_out, int out_size)
{
    const float* Q  = (const float*)d_in[0];
    const float* K  = (const float*)d_in[1];
    const float* V  = (const float*)d_in[2];
    const float* QD = (const float*)d_in[3];
    const float* KD = (const float*)d_in[4];
    const float* VD = (const float*)d_in[5];
    // d_in[6] = attn_mask (causal triu, fixed), d_in[7] = history_len (512) — baked in.
    float* Out = (float*)d_out;

    cudaFuncSetAttribute(fftcc_attn_kernel,
                         cudaFuncAttributeMaxDynamicSharedMemorySize, SMEM_BYTES);
    dim3 grid(Lsz / TILE, Bsz * Hsz);   // (16, 64)
    fftcc_attn_kernel<<<grid, 256, SMEM_BYTES>>>(Q, K, V, QD, KD, VD, Out);
}

// round 3
// speedup vs baseline: 1.1738x; 1.1738x over previous
#include <cuda_runtime.h>
#include <math.h>

namespace {
constexpr int Bsz  = 8;
constexpr int Lsz  = 1024;
constexpr int Hsz  = 8;
constexpr int Esz  = 64;
constexpr int HIST = 512;
constexpr float SCALE = 0.125f;     // 1/sqrt(64)
constexpr int TILE = 64;
constexpr int PSTR = 68;            // Ps stride (floats), 16B-aligned
// Qs(64x64 swizzled) + Ks(64x64 swizzled) + Vs(64x64 plain) + Ps(64x68)
constexpr int SMEM_BYTES = (3 * 64 * 64 + 64 * PSTR) * 4;
}

// physical float offset of logical element e within a swizzled 64-float row
__device__ __forceinline__ int swz_chunk(int row, int ce) { return (ce ^ (row & 15)) << 2; }

__global__ __launch_bounds__(256, 2)
void fftcc_attn_kernel(const float* __restrict__ Q,  const float* __restrict__ K,
                       const float* __restrict__ V,  const float* __restrict__ QD,
                       const float* __restrict__ KD, const float* __restrict__ VD,
                       float* __restrict__ Out)
{
    extern __shared__ float sm[];
    float* Qs = sm;                       // [64][64], chunk-swizzled
    float* Ks = Qs + 64 * 64;             // [64][64], chunk-swizzled
    float* Vs = Ks + 64 * 64;             // [64][64], plain row-major
    float* Ps = Vs + 64 * 64;             // [64][PSTR]

    const int bh = blockIdx.y;
    const int b  = bh >> 3;
    const int h  = bh & 7;
    const int m0  = (int)(gridDim.x - 1 - blockIdx.x) * TILE;  // heaviest first
    const int tid = threadIdx.x;
    const int ty  = tid >> 4;             // 0..15
    const int tx  = tid & 15;             // 0..15
    const int rs  = Hsz * Esz;            // 512
    const int base = (b * Lsz * Hsz + h) * Esz;

    // ---- Load Q tile (q_eff), swizzled float4 stores ----
    {
        const int r0 = tid >> 4;
        const int ce = tid & 15;
        #pragma unroll
        for (int it = 0; it < 4; ++it) {
            const int r = r0 + it * 16;
            const int l = m0 + r;
            const float* src = (l < HIST) ? Q : QD;
            const float4 val = *reinterpret_cast<const float4*>(src + base + l * rs + (ce << 2));
            *reinterpret_cast<float4*>(Qs + r * 64 + swz_chunk(r, ce)) = val;
        }
    }
    __syncthreads();

    // ---- Diagonal replacement scores dS[i] = dot(q_eff[l], keys_drawn[l]) ----
    const bool has_diag_repl = (m0 >= HIST);
    float dS[4] = {0.f, 0.f, 0.f, 0.f};
    if (has_diag_repl && tx == ty) {
        #pragma unroll
        for (int i = 0; i < 4; ++i) {
            const int r = ty + 16 * i;
            const int l = m0 + r;
            const float* kr = KD + base + l * rs;
            float acc = 0.f;
            #pragma unroll
            for (int ce = 0; ce < 16; ++ce) {
                const float4 qv = *reinterpret_cast<const float4*>(Qs + r * 64 + swz_chunk(r, ce));
                const float4 kv = *reinterpret_cast<const float4*>(kr + (ce << 2));
                acc += qv.x * kv.x + qv.y * kv.y + qv.z * kv.z + qv.w * kv.w;
            }
            dS[i] = acc;
        }
    }

    float O[4][4];
    float mrow[4], lsum[4];
    #pragma unroll
    for (int i = 0; i < 4; ++i) {
        mrow[i] = -INFINITY; lsum[i] = 0.f;
        #pragma unroll
        for (int j = 0; j < 4; ++j) O[i][j] = 0.f;
    }

    const int ntiles = (m0 >> 6) + 1;
    for (int t = 0; t < ntiles; ++t) {
        const int n0 = t << 6;
        const bool diag = (n0 == m0);

        __syncthreads();   // previous iteration's readers done with Ks/Vs
        // ---- Load K (swizzled) and V (plain) tiles ----
        {
            const int r0 = tid >> 4;
            const int ce = tid & 15;
            #pragma unroll
            for (int it = 0; it < 4; ++it) {
                const int r = r0 + it * 16;
                const int g = base + (n0 + r) * rs + (ce << 2);
                const float4 kv = *reinterpret_cast<const float4*>(K + g);
                const float4 vv = *reinterpret_cast<const float4*>(V + g);
                *reinterpret_cast<float4*>(Ks + r * 64 + swz_chunk(r, ce)) = kv;
                *reinterpret_cast<float4*>(Vs + r * 64 + (ce << 2)) = vv;
            }
        }
        __syncthreads();

        // ---- S = Q @ K^T : rows ty+16i, cols tx+16j, float4 over E ----
        float S[4][4];
        #pragma unroll
        for (int i = 0; i < 4; ++i)
            #pragma unroll
            for (int j = 0; j < 4; ++j) S[i][j] = 0.f;

        #pragma unroll 4
        for (int ce = 0; ce < 16; ++ce) {
            float4 qv[4], kv[4];
            const int qc = swz_chunk(ty, ce);   // (row&15)==ty for rows ty+16i
            const int kc = swz_chunk(tx, ce);   // (row&15)==tx for rows tx+16j
            #pragma unroll
            for (int i = 0; i < 4; ++i)
                qv[i] = *reinterpret_cast<const float4*>(Qs + (ty + 16 * i) * 64 + qc);
            #pragma unroll
            for (int j = 0; j < 4; ++j)
                kv[j] = *reinterpret_cast<const float4*>(Ks + (tx + 16 * j) * 64 + kc);
            #pragma unroll
            for (int i = 0; i < 4; ++i)
                #pragma unroll
                for (int j = 0; j < 4; ++j)
                    S[i][j] += qv[i].x * kv[j].x + qv[i].y * kv[j].y
                             + qv[i].z * kv[j].z + qv[i].w * kv[j].w;
        }

        // ---- diagonal substitution (pre-scale), scale, causal mask ----
        if (diag && has_diag_repl && tx == ty) {
            #pragma unroll
            for (int i = 0; i < 4; ++i) S[i][i] = dS[i];
        }
        #pragma unroll
        for (int i = 0; i < 4; ++i)
            #pragma unroll
            for (int j = 0; j < 4; ++j) S[i][j] *= SCALE;
        if (diag) {
            // col = tx+16j, row = ty+16i : mask iff j>i || (j==i && tx>ty)
            #pragma unroll
            for (int i = 0; i < 4; ++i)
                #pragma unroll
                for (int j = 0; j < 4; ++j)
                    if (j > i || (j == i && tx > ty)) S[i][j] = -INFINITY;
        }

        // ---- online softmax (row reductions over 16 tx-lanes) ----
        #pragma unroll
        for (int i = 0; i < 4; ++i) {
            float mx = fmaxf(fmaxf(S[i][0], S[i][1]), fmaxf(S[i][2], S[i][3]));
            #pragma unroll
            for (int o = 8; o > 0; o >>= 1)
                mx = fmaxf(mx, __shfl_xor_sync(0xffffffffu, mx, o));
            const float nm   = fmaxf(mrow[i], mx);
            const float corr = __expf(mrow[i] - nm);
            mrow[i] = nm;
            float rsum = 0.f;
            #pragma unroll
            for (int j = 0; j < 4; ++j) {
                const float p = __expf(S[i][j] - nm);
                S[i][j] = p;
                rsum += p;
            }
            #pragma unroll
            for (int o = 8; o > 0; o >>= 1)
                rsum += __shfl_xor_sync(0xffffffffu, rsum, o);
            lsum[i] = lsum[i] * corr + rsum;
            #pragma unroll
            for (int j = 0; j < 4; ++j) O[i][j] *= corr;
            float* pr = Ps + (ty + 16 * i) * PSTR;
            #pragma unroll
            for (int j = 0; j < 4; ++j) pr[tx + 16 * j] = S[i][j];
        }
        // P rows ty+16i are produced & consumed within this warp's ty-halves
        __syncwarp();

        // ---- O += P @ V : float4 over s (pv) and over E (vv) ----
        #pragma unroll 4
        for (int s4 = 0; s4 < 16; ++s4) {
            float4 pv[4];
            #pragma unroll
            for (int i = 0; i < 4; ++i)
                pv[i] = *reinterpret_cast<const float4*>(Ps + (ty + 16 * i) * PSTR + (s4 << 2));
            #pragma unroll
            for (int k = 0; k < 4; ++k) {
                const int s = (s4 << 2) + k;
                const float4 vv = *reinterpret_cast<const float4*>(Vs + s * 64 + (tx << 2));
                #pragma unroll
                for (int i = 0; i < 4; ++i) {
                    const float p = (k == 0) ? pv[i].x : (k == 1) ? pv[i].y
                                  : (k == 2) ? pv[i].z : pv[i].w;
                    O[i][0] += p * vv.x; O[i][1] += p * vv.y;
                    O[i][2] += p * vv.z; O[i][3] += p * vv.w;
                }
            }
        }

        // ---- diagonal value substitution: O += P[l][l]*(vd[l]-v[l]) ----
        if (diag && has_diag_repl) {
            #pragma unroll
            for (int i = 0; i < 4; ++i) {
                const int r = ty + 16 * i;
                const int l = m0 + r;
                const float pd = Ps[r * PSTR + r];
                const float4 vdr = *reinterpret_cast<const float4*>(VD + base + l * rs + (tx << 2));
                const float4 vv  = *reinterpret_cast<const float4*>(Vs + r * 64 + (tx << 2));
                O[i][0] += pd * (vdr.x - vv.x);
                O[i][1] += pd * (vdr.y - vv.y);
                O[i][2] += pd * (vdr.z - vv.z);
                O[i][3] += pd * (vdr.w - vv.w);
            }
        }
    }

    // ---- epilogue ----
    #pragma unroll
    for (int i = 0; i < 4; ++i) {
        const int r = ty + 16 * i;
        const int l = m0 + r;
        const float inv = 1.0f / lsum[i];
        const float4 o4 = make_float4(O[i][0] * inv, O[i][1] * inv,
                                      O[i][2] * inv, O[i][3] * inv);
        *reinterpret_cast<float4*>(Out + base + l * rs + (tx << 2)) = o4;
    }
}

extern "C" void kernel_launch(void* const* d_in, const int* in_sizes, int n_in,
                              void* d_out, int out_size)
{
    const float* Q  = (const float*)d_in[0];
    const float* K  = (const float*)d_in[1];
    const float* V  = (const float*)d_in[2];
    const float* QD = (const float*)d_in[3];
    const float* KD = (const float*)d_in[4];
    const float* VD = (const float*)d_in[5];
    float* Out = (float*)d_out;

    cudaFuncSetAttribute(fftcc_attn_kernel,
                         cudaFuncAttributeMaxDynamicSharedMemorySize, SMEM_BYTES);
    dim3 grid(Lsz / TILE, Bsz * Hsz);   // (16, 64)
    fftcc_attn_kernel<<<grid, 256, SMEM_BYTES>>>(Q, K, V, QD, KD, VD, Out);
}